// round 1
// baseline (speedup 1.0000x reference)
#include <cuda_runtime.h>

#define NL 6
#define NB 6
#define NS 7
#define DD 512
#define NH 8
#define HD 64
#define FF 2048
#define TD 1536   // 3*D

// ---------------- scratch (device globals; no allocation allowed) ----------
__device__ __align__(16) float g_kv[NL*5*NS*1024];   // k,v for l, b=1..5, s
__device__ __align__(16) float g_q0[NL*5*DD];        // q token0 for l, b=1..5
__device__ __align__(16) float g_vm[NL*5*DD];        // msg[b,0,:] per layer
__device__ __align__(16) float g_aggv[NL*DD];        // sigmoid agg_verb per layer
__device__ __align__(16) float g_x0[NS*DD];          // evolving x[0]
__device__ __align__(16) float g_qkv0[NS*TD];
__device__ __align__(16) float g_ctx[6*DD];          // ctx for q tokens 1..6
__device__ __align__(16) float g_msgN[6*DD];         // msg[0,1:,:]
__device__ __align__(16) float g_aggn[DD];
__device__ __align__(16) float g_h[NS*DD];           // post LN1/LN3 (row0 = t)
__device__ __align__(16) float g_hid[NS*FF];
__device__ __align__(16) float g_y[NS*DD];           // ffn out + residual

// ---------------- helpers ---------------------------------------------------
__device__ __forceinline__ float warp_reduce(float v) {
#pragma unroll
    for (int o = 16; o; o >>= 1) v += __shfl_xor_sync(0xffffffffu, v, o);
    return v;
}

// dot of length 4*n4; w global (coalesced per warp), x in smem. all 32 lanes call.
__device__ __forceinline__ float warp_dot(const float* __restrict__ w,
                                          const float* __restrict__ x, int n4) {
    const float4* w4 = reinterpret_cast<const float4*>(w);
    const float4* x4 = reinterpret_cast<const float4*>(x);
    float acc = 0.f;
    for (int i = (threadIdx.x & 31); i < n4; i += 32) {
        float4 a = __ldg(&w4[i]);
        float4 b = x4[i];
        acc = fmaf(a.x, b.x, fmaf(a.y, b.y, fmaf(a.z, b.z, fmaf(a.w, b.w, acc))));
    }
    return warp_reduce(acc);
}

// warp-collective layernorm of a 512 row. add may be null.
__device__ __forceinline__ void warp_ln_row(const float* __restrict__ xin,
                                            const float* __restrict__ add,
                                            const float* __restrict__ w,
                                            const float* __restrict__ b,
                                            float* __restrict__ out) {
    int lane = threadIdx.x & 31;
    float v[16];
    float sum = 0.f;
#pragma unroll
    for (int j = 0; j < 16; j++) {
        float t = xin[j*32 + lane];
        if (add) t += add[j*32 + lane];
        v[j] = t; sum += t;
    }
    sum = warp_reduce(sum);
    float mu = sum * (1.f/512.f);
    float sq = 0.f;
#pragma unroll
    for (int j = 0; j < 16; j++) { float d = v[j] - mu; sq += d*d; }
    sq = warp_reduce(sq);
    float rs = rsqrtf(sq * (1.f/512.f) + 1e-5f);
#pragma unroll
    for (int j = 0; j < 16; j++)
        out[j*32 + lane] = (v[j] - mu) * rs * w[j*32 + lane] + b[j*32 + lane];
}

// ---------------- precompute phase (independent of evolving state) ---------
// P1: k,v (and q token0) for all (l, b=1..5). grid 420, block 256.
__global__ void p1_kv(const float* __restrict__ feat, const float* __restrict__ role,
                      const float* __restrict__ in_w, const float* __restrict__ in_b) {
    int bx = blockIdx.x;
    int half = bx & 1;
    int idx = bx >> 1;               // 0..209
    int l = idx / 35; int rem = idx % 35;
    int b = rem / 7 + 1; int s = rem % 7;
    __shared__ __align__(16) float src[DD];
    int tid = threadIdx.x;
    for (int d = tid; d < DD; d += 256) {
        float v = feat[(b*NS + s)*DD + d];
        if (s > 0) v += role[(b*6 + (s-1))*DD + d];
        src[d] = v;
    }
    __syncthreads();
    int warp = tid >> 5;
    const float* wbase = in_w + (size_t)l*TD*DD;
    const float* bbase = in_b + l*TD;
    float* out = g_kv + ((l*5 + (b-1))*NS + s)*1024;
    for (int e = half*512 + warp; e < half*512 + 512; e += 8) {
        int row = 512 + e;
        float v = warp_dot(wbase + (size_t)row*DD, src, DD/4) + bbase[row];
        if ((tid & 31) == 0) out[e] = v;
    }
    if (half == 0 && s == 0) {
        float* q0 = g_q0 + (l*5 + (b-1))*DD;
        for (int e = warp; e < DD; e += 8) {
            float v = warp_dot(wbase + (size_t)e*DD, src, DD/4) + bbase[e];
            if ((tid & 31) == 0) q0[e] = v;
        }
    }
}

// P2: attention token0 + out-proj for (l, b=1..5). grid 30, block 256.
__global__ void p2_attn(const float* __restrict__ out_w, const float* __restrict__ out_b) {
    int l = blockIdx.x / 5, b5 = blockIdx.x % 5;
    int tid = threadIdx.x;
    __shared__ __align__(16) float sq[DD];
    __shared__ __align__(16) float sk[NS*DD];
    __shared__ float ssc[NH*NS];
    __shared__ __align__(16) float sctx[DD];
    const float* q0 = g_q0 + (l*5 + b5)*DD;
    const float* kv = g_kv + (l*5 + b5)*NS*1024;
    for (int i = tid; i < DD; i += 256) sq[i] = q0[i];
    for (int i = tid; i < NS*DD; i += 256) { int s = i >> 9, d = i & 511; sk[i] = kv[s*1024 + d]; }
    __syncthreads();
    if (tid < NH*NS) {
        int h = tid / NS, s = tid % NS;
        float a = 0.f;
        for (int d = 0; d < HD; d++) a += sq[h*HD + d] * sk[s*DD + h*HD + d];
        ssc[tid] = a * 0.125f;
    }
    __syncthreads();
    if (tid < NH) {
        float m = -1e30f;
        for (int s = 0; s < NS; s++) m = fmaxf(m, ssc[tid*NS + s]);
        float e[NS]; float sum = 0.f;
        for (int s = 0; s < NS; s++) { e[s] = expf(ssc[tid*NS + s] - m); sum += e[s]; }
        for (int s = 0; s < NS; s++) ssc[tid*NS + s] = e[s] / sum;
    }
    __syncthreads();
    for (int ch = tid; ch < DD; ch += 256) {
        int h = ch >> 6;
        float a = 0.f;
        for (int s = 0; s < NS; s++) a += ssc[h*NS + s] * kv[s*1024 + 512 + ch];
        sctx[ch] = a;
    }
    __syncthreads();
    int warp = tid >> 5;
    float* vm = g_vm + (l*5 + b5)*DD;
    for (int e = warp; e < DD; e += 8) {
        float v = warp_dot(out_w + ((size_t)l*DD + e)*DD, sctx, 128) + out_b[l*DD + e];
        if ((tid & 31) == 0) vm[e] = v;
    }
}

// P3: agg_verb per layer. grid 48, block 256.
__global__ void p3_aggv(const float* __restrict__ a1_w, const float* __restrict__ a1_b) {
    int l = blockIdx.x / 8, c = blockIdx.x % 8;
    __shared__ __align__(16) float vm[5*DD];
    int tid = threadIdx.x;
    const float* src = g_vm + l*5*DD;
    for (int i = tid; i < 5*DD; i += 256) vm[i] = src[i];
    __syncthreads();
    int warp = tid >> 5;
    for (int e = c*64 + warp; e < c*64 + 64; e += 8) {
        float v = warp_dot(a1_w + ((size_t)l*DD + e)*2560, vm, 640) + a1_b[l*DD + e];
        if ((tid & 31) == 0) g_aggv[l*DD + e] = 1.f / (1.f + expf(-v));
    }
}

__global__ void k_init(const float* __restrict__ feat) {
    int i = blockIdx.x*256 + threadIdx.x;
    if (i < NS*DD) g_x0[i] = feat[i];  // features[0]
}

// ---------------- sequential phase ------------------------------------------
// S1: qkv for batch 0. grid 168 (7 tokens x 24 chunks), block 256.
__global__ void s1_qkv(int l, const float* __restrict__ role,
                       const float* __restrict__ in_w, const float* __restrict__ in_b) {
    int s = blockIdx.x / 24, c = blockIdx.x % 24;
    __shared__ __align__(16) float src[DD];
    int tid = threadIdx.x;
    for (int d = tid; d < DD; d += 256) {
        float v = g_x0[s*DD + d];
        if (s > 0) v += role[(s-1)*DD + d];   // batch 0 role tokens
        src[d] = v;
    }
    __syncthreads();
    int warp = tid >> 5;
    const float* wbase = in_w + (size_t)l*TD*DD;
    for (int e = c*64 + warp; e < c*64 + 64; e += 8) {
        float v = warp_dot(wbase + (size_t)e*DD, src, 128) + in_b[l*TD + e];
        if ((tid & 31) == 0) g_qkv0[s*TD + e] = v;
    }
}

// S2: attention batch 0, queries tokens 1..6. grid 1, block 256.
__global__ void s2_attn() {
    int tid = threadIdx.x;
    __shared__ __align__(16) float sk[NS*DD];
    __shared__ __align__(16) float sq[6*DD];
    __shared__ float satt[6*NH*NS];   // 336
    for (int i = tid; i < NS*DD; i += 256) { int s = i >> 9, d = i & 511; sk[i] = g_qkv0[s*TD + 512 + d]; }
    for (int i = tid; i < 6*DD;  i += 256) { int q = i >> 9, d = i & 511; sq[i] = g_qkv0[(q+1)*TD + d]; }
    __syncthreads();
    for (int t = tid; t < 336; t += 256) {
        int qi = t / 56, r = t % 56, h = r / 7, s = r % 7;
        float a = 0.f;
        for (int d = 0; d < HD; d++) a += sq[qi*DD + h*HD + d] * sk[s*DD + h*HD + d];
        satt[t] = a * 0.125f;
    }
    __syncthreads();
    if (tid < 48) {
        int base = tid * 7;
        float m = -1e30f;
        for (int s = 0; s < 7; s++) m = fmaxf(m, satt[base + s]);
        float e[7]; float sum = 0.f;
        for (int s = 0; s < 7; s++) { e[s] = expf(satt[base + s] - m); sum += e[s]; }
        for (int s = 0; s < 7; s++) satt[base + s] = e[s] / sum;
    }
    __syncthreads();
    for (int i = tid; i < 6*DD; i += 256) {
        int qi = i >> 9, ch = i & 511, h = ch >> 6;
        float a = 0.f;
        for (int s = 0; s < 7; s++) a += satt[qi*56 + h*7 + s] * g_qkv0[s*TD + 1024 + ch];
        g_ctx[i] = a;
    }
}

// S3: out-proj msg[0,1:,:]. grid 48, block 256.
__global__ void s3_msg(int l, const float* __restrict__ out_w, const float* __restrict__ out_b) {
    int r = blockIdx.x / 8, c = blockIdx.x % 8;
    __shared__ __align__(16) float ctx[DD];
    int tid = threadIdx.x;
    for (int i = tid; i < DD; i += 256) ctx[i] = g_ctx[r*DD + i];
    __syncthreads();
    int warp = tid >> 5;
    for (int e = c*64 + warp; e < c*64 + 64; e += 8) {
        float v = warp_dot(out_w + ((size_t)l*DD + e)*DD, ctx, 128) + out_b[l*DD + e];
        if ((tid & 31) == 0) g_msgN[r*DD + e] = v;
    }
}

// S4: agg_noun. grid 64 (8 outputs each), block 256.
__global__ void s4_aggn(int l, const float* __restrict__ a2_w, const float* __restrict__ a2_b) {
    __shared__ __align__(16) float nm[6*DD];
    int tid = threadIdx.x;
    for (int i = tid; i < 6*DD; i += 256) nm[i] = g_msgN[i];
    __syncthreads();
    int warp = tid >> 5;
    int e = blockIdx.x*8 + warp;
    float v = warp_dot(a2_w + ((size_t)l*DD + e)*3072, nm, 768) + a2_b[l*DD + e];
    if ((tid & 31) == 0) g_aggn[e] = 1.f / (1.f + expf(-v));
}

// S5: LN1 (rows 1..6, + agg_verb) and LN3 (row 0, + agg_noun). grid 1, block 256.
__global__ void s5_ln13(int l, const float* __restrict__ ln1w, const float* __restrict__ ln1b,
                        const float* __restrict__ ln3w, const float* __restrict__ ln3b) {
    int warp = threadIdx.x >> 5;
    if (warp >= 7) return;
    if (warp == 0)
        warp_ln_row(g_x0, g_aggn, ln3w + l*DD, ln3b + l*DD, g_h);
    else
        warp_ln_row(g_x0 + warp*DD, g_aggv + l*DD, ln1w + l*DD, ln1b + l*DD, g_h + warp*DD);
}

// S6: FFN up (relu). grid 224 (7 rows x 32 chunks), block 256.
__global__ void s6_up(int l, const float* __restrict__ f1w1, const float* __restrict__ f1b1,
                      const float* __restrict__ f2w1, const float* __restrict__ f2b1) {
    int r = blockIdx.x / 32, c = blockIdx.x % 32;
    __shared__ __align__(16) float h[DD];
    int tid = threadIdx.x;
    for (int i = tid; i < DD; i += 256) h[i] = g_h[r*DD + i];
    __syncthreads();
    const float* w  = (r == 0) ? (f2w1 + (size_t)l*FF*DD) : (f1w1 + (size_t)l*FF*DD);
    const float* bb = (r == 0) ? (f2b1 + l*FF) : (f1b1 + l*FF);
    int warp = tid >> 5;
    for (int e = c*64 + warp; e < c*64 + 64; e += 8) {
        float v = warp_dot(w + (size_t)e*DD, h, 128) + bb[e];
        if ((tid & 31) == 0) g_hid[r*FF + e] = fmaxf(v, 0.f);
    }
}

// S7: FFN down + residual. grid 224 (7 rows x 32 chunks of 16), block 256.
__global__ void s7_down(int l, const float* __restrict__ f1w2, const float* __restrict__ f1b2,
                        const float* __restrict__ f2w2, const float* __restrict__ f2b2) {
    int r = blockIdx.x / 32, c = blockIdx.x % 32;
    __shared__ __align__(16) float h[FF];
    int tid = threadIdx.x;
    for (int i = tid; i < FF; i += 256) h[i] = g_hid[r*FF + i];
    __syncthreads();
    const float* w  = (r == 0) ? (f2w2 + (size_t)l*DD*FF) : (f1w2 + (size_t)l*DD*FF);
    const float* bb = (r == 0) ? (f2b2 + l*DD) : (f1b2 + l*DD);
    int warp = tid >> 5;
    for (int e = c*16 + warp; e < c*16 + 16; e += 8) {
        float v = warp_dot(w + (size_t)e*FF, h, 512) + bb[e] + g_h[r*DD + e];
        if ((tid & 31) == 0) g_y[r*DD + e] = v;
    }
}

// S8: LN2 (rows 1..6) / LN4 (row 0) -> new x0. grid 1, block 256.
__global__ void s8_ln24(int l, const float* __restrict__ ln2w, const float* __restrict__ ln2b,
                        const float* __restrict__ ln4w, const float* __restrict__ ln4b) {
    int warp = threadIdx.x >> 5;
    if (warp >= 7) return;
    if (warp == 0)
        warp_ln_row(g_y, nullptr, ln4w + l*DD, ln4b + l*DD, g_x0);
    else
        warp_ln_row(g_y + warp*DD, nullptr, ln2w + l*DD, ln2b + l*DD, g_x0 + warp*DD);
}

__global__ void k_out(float* __restrict__ out) {
    int i = blockIdx.x*256 + threadIdx.x;
    if (i < NS*DD) out[i] = g_x0[i];
}

// ---------------- host -------------------------------------------------------
extern "C" void kernel_launch(void* const* d_in, const int* in_sizes, int n_in,
                              void* d_out, int out_size) {
    const float* feat = (const float*)d_in[0];
    const float* role = (const float*)d_in[1];
    const float* in_w = (const float*)d_in[2];
    const float* in_b = (const float*)d_in[3];
    const float* out_w = (const float*)d_in[4];
    const float* out_b = (const float*)d_in[5];
    const float* ln1w = (const float*)d_in[6];
    const float* ln1b = (const float*)d_in[7];
    const float* ln2w = (const float*)d_in[8];
    const float* ln2b = (const float*)d_in[9];
    const float* ln3w = (const float*)d_in[10];
    const float* ln3b = (const float*)d_in[11];
    const float* ln4w = (const float*)d_in[12];
    const float* ln4b = (const float*)d_in[13];
    const float* f1w1 = (const float*)d_in[14];
    const float* f1b1 = (const float*)d_in[15];
    const float* f1w2 = (const float*)d_in[16];
    const float* f1b2 = (const float*)d_in[17];
    const float* f2w1 = (const float*)d_in[18];
    const float* f2b1 = (const float*)d_in[19];
    const float* f2w2 = (const float*)d_in[20];
    const float* f2b2 = (const float*)d_in[21];
    const float* a1w  = (const float*)d_in[22];
    const float* a1b  = (const float*)d_in[23];
    const float* a2w  = (const float*)d_in[24];
    const float* a2b  = (const float*)d_in[25];

    k_init<<<14, 256>>>(feat);
    p1_kv<<<420, 256>>>(feat, role, in_w, in_b);
    p2_attn<<<30, 256>>>(out_w, out_b);
    p3_aggv<<<48, 256>>>(a1w, a1b);

    for (int l = 0; l < NL; l++) {
        s1_qkv<<<168, 256>>>(l, role, in_w, in_b);
        s2_attn<<<1, 256>>>();
        s3_msg<<<48, 256>>>(l, out_w, out_b);
        s4_aggn<<<64, 256>>>(l, a2w, a2b);
        s5_ln13<<<1, 256>>>(l, ln1w, ln1b, ln3w, ln3b);
        s6_up<<<224, 256>>>(l, f1w1, f1b1, f2w1, f2b1);
        s7_down<<<224, 256>>>(l, f1w2, f1b2, f2w2, f2b2);
        s8_ln24<<<1, 256>>>(l, ln2w, ln2b, ln4w, ln4b);
    }
    k_out<<<14, 256>>>((float*)d_out);
}

// round 2
// speedup vs baseline: 2.7492x; 2.7492x over previous
#include <cuda_runtime.h>

#define NBLK 148
#define NTHR 256
#define NWARP (NBLK*8)
#define NL 6
#define DD 512
#define FF 2048
#define TD 1536

// ---------------- device scratch ----------------
__device__ __align__(16) float g_src35[35*DD];
__device__ __align__(16) float g_kv[NL*5*7*1024];
__device__ __align__(16) float g_q0[NL*5*DD];
__device__ __align__(16) float g_ctx5[NL*5*DD];
__device__ __align__(16) float g_vm[NL*5*DD];
__device__ __align__(16) float g_aggv[NL*DD];
__device__ __align__(16) float g_x0[7*DD];
__device__ __align__(16) float g_qkv0[7*TD];
__device__ __align__(16) float g_msgN[6*DD];
__device__ __align__(16) float g_aggn[DD];
__device__ __align__(16) float g_h[7*DD];
__device__ __align__(16) float g_hid[7*FF];
__device__ __align__(16) float g_y[7*DD];
__device__ unsigned g_bar;

// ---------------- helpers ----------------
__device__ __forceinline__ float wred(float v) {
#pragma unroll
    for (int o = 16; o; o >>= 1) v += __shfl_xor_sync(0xffffffffu, v, o);
    return v;
}
__device__ __forceinline__ float d4(float4 a, float4 b) {
    return fmaf(a.x, b.x, fmaf(a.y, b.y, fmaf(a.z, b.z, a.w * b.w)));
}
__device__ __forceinline__ void gridbar() {
    __syncthreads();
    if (threadIdx.x == 0) {
        __threadfence();
        unsigned old = atomicAdd(&g_bar, 1u);
        unsigned target = (old / NBLK + 1u) * NBLK;
        while (*((volatile unsigned*)&g_bar) < target) {}
    }
    __syncthreads();
    __threadfence();
}
// warp-collective LN of a 512-row; add may be null
__device__ __forceinline__ void ln_row(const float* __restrict__ x,
                                       const float* __restrict__ add,
                                       const float* __restrict__ w,
                                       const float* __restrict__ b,
                                       float* __restrict__ out) {
    int lane = threadIdx.x & 31;
    float v[16]; float s = 0.f;
#pragma unroll
    for (int j = 0; j < 16; j++) {
        float t = x[j*32 + lane];
        if (add) t += add[j*32 + lane];
        v[j] = t; s += t;
    }
    s = wred(s);
    float mu = s * (1.f/512.f);
    float q = 0.f;
#pragma unroll
    for (int j = 0; j < 16; j++) { float d = v[j] - mu; q += d*d; }
    q = wred(q);
    float rs = rsqrtf(q * (1.f/512.f) + 1e-5f);
#pragma unroll
    for (int j = 0; j < 16; j++)
        out[j*32 + lane] = (v[j] - mu) * rs * w[j*32 + lane] + b[j*32 + lane];
}

__global__ void __launch_bounds__(NTHR)
fused_kernel(const float* __restrict__ feat, const float* __restrict__ role,
             const float* __restrict__ in_w, const float* __restrict__ in_b,
             const float* __restrict__ out_w, const float* __restrict__ out_b,
             const float* __restrict__ ln1w, const float* __restrict__ ln1b,
             const float* __restrict__ ln2w, const float* __restrict__ ln2b,
             const float* __restrict__ ln3w, const float* __restrict__ ln3b,
             const float* __restrict__ ln4w, const float* __restrict__ ln4b,
             const float* __restrict__ f1w1, const float* __restrict__ f1b1,
             const float* __restrict__ f1w2, const float* __restrict__ f1b2,
             const float* __restrict__ f2w1, const float* __restrict__ f2b1,
             const float* __restrict__ f2w2, const float* __restrict__ f2b2,
             const float* __restrict__ a1w, const float* __restrict__ a1b,
             const float* __restrict__ a2w, const float* __restrict__ a2b,
             float* __restrict__ out)
{
    extern __shared__ float sm[];
    const int tid = threadIdx.x, lane = tid & 31, warp = tid >> 5;
    const int gw = blockIdx.x * 8 + warp;
    const int gt = blockIdx.x * NTHR + tid;

    // ---- Phase A: src vectors for batches 1..5 (constant across layers) ----
    for (int i = gt; i < 35*DD; i += NBLK*NTHR) {
        int b5 = i / (7*DD); int rem = i % (7*DD); int s = rem / DD; int d = rem % DD;
        float v = feat[((b5+1)*7 + s)*DD + d];
        if (s > 0) v += role[((b5+1)*6 + (s-1))*DD + d];
        g_src35[i] = v;
    }
    gridbar();

    // ---- Phase P1: K,V for all (l,b>=1,s) and Q(token0) for all (l,b>=1) ----
    for (int i = tid; i < 35*DD; i += NTHR) sm[i] = g_src35[i];
    __syncthreads();
    for (int t = gw; t < NL*1024 + NL*DD; t += NWARP) {
        if (t < NL*1024) {
            int l = t >> 10, e = t & 1023;
            const float4* wr = (const float4*)(in_w + ((size_t)l*TD + 512 + e)*DD);
            float4 wv[4];
#pragma unroll
            for (int i = 0; i < 4; i++) wv[i] = __ldg(&wr[lane + 32*i]);
            float bias = in_b[l*TD + 512 + e];
            for (int bs = 0; bs < 35; bs++) {
                const float4* s4 = (const float4*)(sm + bs*DD);
                float a = 0.f;
#pragma unroll
                for (int i = 0; i < 4; i++) a += d4(wv[i], s4[lane + 32*i]);
                a = wred(a);
                if (lane == 0)
                    g_kv[((size_t)(l*5 + bs/7)*7 + bs%7)*1024 + e] = a + bias;
            }
        } else {
            int t2 = t - NL*1024;
            int l = t2 / DD, e = t2 % DD;
            const float4* wr = (const float4*)(in_w + ((size_t)l*TD + e)*DD);
            float4 wv[4];
#pragma unroll
            for (int i = 0; i < 4; i++) wv[i] = __ldg(&wr[lane + 32*i]);
            float bias = in_b[l*TD + e];
            for (int b5 = 0; b5 < 5; b5++) {
                const float4* s4 = (const float4*)(sm + (b5*7)*DD);
                float a = 0.f;
#pragma unroll
                for (int i = 0; i < 4; i++) a += d4(wv[i], s4[lane + 32*i]);
                a = wred(a);
                if (lane == 0) g_q0[(l*5 + b5)*DD + e] = a + bias;
            }
        }
    }
    gridbar();

    // ---- Phase P2a: attention token0 for (l, b>=1): 30 CTA tasks ----
    if (blockIdx.x < 30) {
        int l = blockIdx.x / 5, b5 = blockIdx.x % 5;
        float* sq = sm; float* sk = sm + DD; float* satt = sm + DD + 7*DD;
        const float* kvb = g_kv + (size_t)(l*5 + b5)*7*1024;
        for (int i = tid; i < DD; i += NTHR) sq[i] = g_q0[(l*5 + b5)*DD + i];
        for (int i = tid; i < 7*DD; i += NTHR) { int s = i >> 9, d = i & 511; sk[i] = kvb[s*1024 + d]; }
        __syncthreads();
        if (tid < 56) {
            int h = tid / 7, s = tid % 7;
            float a = 0.f;
            for (int d = 0; d < 64; d++) a += sq[h*64 + d] * sk[s*DD + h*64 + d];
            satt[tid] = a * 0.125f;
        }
        __syncthreads();
        if (tid < 8) {
            float m = -1e30f;
            for (int s = 0; s < 7; s++) m = fmaxf(m, satt[tid*7 + s]);
            float e[7], su = 0.f;
            for (int s = 0; s < 7; s++) { e[s] = expf(satt[tid*7 + s] - m); su += e[s]; }
            for (int s = 0; s < 7; s++) satt[tid*7 + s] = e[s] / su;
        }
        __syncthreads();
        for (int ch = tid; ch < DD; ch += NTHR) {
            int h = ch >> 6;
            float a = 0.f;
            for (int s = 0; s < 7; s++) a += satt[h*7 + s] * kvb[s*1024 + 512 + ch];
            g_ctx5[(l*5 + b5)*DD + ch] = a;
        }
    }
    gridbar();

    // ---- Phase P2b: verb msgs: out-proj of ctx for (l,b>=1) ----
    for (int i = tid; i < 30*DD; i += NTHR) sm[i] = g_ctx5[i];
    __syncthreads();
    for (int t = gw; t < NL*DD; t += NWARP) {
        int l = t / DD, e = t % DD;
        const float4* wr = (const float4*)(out_w + ((size_t)l*DD + e)*DD);
        float4 wv[4];
#pragma unroll
        for (int i = 0; i < 4; i++) wv[i] = __ldg(&wr[lane + 32*i]);
        float bias = out_b[l*DD + e];
        for (int b5 = 0; b5 < 5; b5++) {
            const float4* s4 = (const float4*)(sm + (l*5 + b5)*DD);
            float a = 0.f;
#pragma unroll
            for (int i = 0; i < 4; i++) a += d4(wv[i], s4[lane + 32*i]);
            a = wred(a);
            if (lane == 0) g_vm[(l*5 + b5)*DD + e] = a + bias;
        }
    }
    gridbar();

    // ---- Phase P3: agg_verb for all layers ----
    for (int i = tid; i < 30*DD; i += NTHR) sm[i] = g_vm[i];
    __syncthreads();
    for (int t = gw; t < NL*DD; t += NWARP) {
        int l = t / DD, e = t % DD;
        const float4* wr = (const float4*)(a1w + ((size_t)l*DD + e)*2560);
        const float4* s4 = (const float4*)(sm + l*5*DD);
        float a = 0.f;
#pragma unroll
        for (int i = 0; i < 20; i++) a += d4(__ldg(&wr[lane + 32*i]), s4[lane + 32*i]);
        a = wred(a);
        if (lane == 0) g_aggv[l*DD + e] = 1.f / (1.f + expf(-(a + a1b[l*DD + e])));
    }
    gridbar();

    // ================= serial layer loop =================
    for (int l = 0; l < NL; l++) {
        // ---- s1: x0 = LN24(y_prev) (redundant per CTA), src = x0 + role, qkv ----
        float* sx0 = sm;           // 3584
        float* ssrc = sm + 3584;   // 3584
        if (l == 0) {
            for (int i = tid; i < 7*DD; i += NTHR) sx0[i] = feat[i];
        } else {
            if (warp < 7) {
                const float* w = (warp == 0) ? (ln4w + (l-1)*DD) : (ln2w + (l-1)*DD);
                const float* b = (warp == 0) ? (ln4b + (l-1)*DD) : (ln2b + (l-1)*DD);
                ln_row(g_y + warp*DD, nullptr, w, b, sx0 + warp*DD);
            }
        }
        __syncthreads();
        for (int i = tid; i < 7*DD; i += NTHR) {
            int s = i >> 9, d = i & 511;
            float v = sx0[i];
            if (s > 0) v += role[(s-1)*DD + d];
            ssrc[i] = v;
        }
        if (blockIdx.x == 0)
            for (int i = tid; i < 7*DD; i += NTHR) g_x0[i] = sx0[i];
        __syncthreads();
        for (int t = gw; t < TD; t += NWARP) {
            const float4* wr = (const float4*)(in_w + ((size_t)l*TD + t)*DD);
            float4 wv[4];
#pragma unroll
            for (int i = 0; i < 4; i++) wv[i] = __ldg(&wr[lane + 32*i]);
            float bias = in_b[l*TD + t];
            for (int s = 0; s < 7; s++) {
                const float4* s4 = (const float4*)(ssrc + s*DD);
                float a = 0.f;
#pragma unroll
                for (int i = 0; i < 4; i++) a += d4(wv[i], s4[lane + 32*i]);
                a = wred(a);
                if (lane == 0) g_qkv0[s*TD + t] = a + bias;
            }
        }
        gridbar();

        // ---- s3: attention (redundant per CTA) + msg out-proj (grid) ----
        {
            float* sqkv = sm;              // 10752
            float* sctx = sm + 10752;      // 3072
            float* satt = sm + 13824;      // 336
            for (int i = tid; i < 7*TD; i += NTHR) sqkv[i] = g_qkv0[i];
            __syncthreads();
            for (int t = tid; t < 336; t += NTHR) {
                int qi = t / 56, r = t % 56, h = r / 7, s = r % 7;
                float a = 0.f;
                for (int d = 0; d < 64; d++)
                    a += sqkv[(qi+1)*TD + h*64 + d] * sqkv[s*TD + 512 + h*64 + d];
                satt[t] = a * 0.125f;
            }
            __syncthreads();
            if (tid < 48) {
                float m = -1e30f;
                for (int s = 0; s < 7; s++) m = fmaxf(m, satt[tid*7 + s]);
                float e[7], su = 0.f;
                for (int s = 0; s < 7; s++) { e[s] = expf(satt[tid*7 + s] - m); su += e[s]; }
                for (int s = 0; s < 7; s++) satt[tid*7 + s] = e[s] / su;
            }
            __syncthreads();
            for (int i = tid; i < 6*DD; i += NTHR) {
                int qi = i >> 9, ch = i & 511, h = ch >> 6;
                float a = 0.f;
                for (int s = 0; s < 7; s++) a += satt[qi*56 + h*7 + s] * sqkv[s*TD + 1024 + ch];
                sctx[i] = a;
            }
            __syncthreads();
            for (int t = gw; t < DD; t += NWARP) {
                const float4* wr = (const float4*)(out_w + ((size_t)l*DD + t)*DD);
                float4 wv[4];
#pragma unroll
                for (int i = 0; i < 4; i++) wv[i] = __ldg(&wr[lane + 32*i]);
                float bias = out_b[l*DD + t];
                for (int r = 0; r < 6; r++) {
                    const float4* s4 = (const float4*)(sctx + r*DD);
                    float a = 0.f;
#pragma unroll
                    for (int i = 0; i < 4; i++) a += d4(wv[i], s4[lane + 32*i]);
                    a = wred(a);
                    if (lane == 0) g_msgN[r*DD + t] = a + bias;
                }
            }
        }
        gridbar();

        // ---- s4: agg_noun ----
        for (int i = tid; i < 6*DD; i += NTHR) sm[i] = g_msgN[i];
        __syncthreads();
        for (int t = gw; t < DD; t += NWARP) {
            const float4* wr = (const float4*)(a2w + ((size_t)l*DD + t)*3072);
            const float4* s4 = (const float4*)sm;
            float a = 0.f;
#pragma unroll
            for (int i = 0; i < 24; i++) a += d4(__ldg(&wr[lane + 32*i]), s4[lane + 32*i]);
            a = wred(a);
            if (lane == 0) g_aggn[t] = 1.f / (1.f + expf(-(a + a2b[l*DD + t])));
        }
        gridbar();

        // ---- s6: LN13 (redundant per CTA) + FFN up ----
        {
            float* sh = sm;  // 3584
            if (warp < 7) {
                const float* addv = (warp == 0) ? g_aggn : (g_aggv + l*DD);
                const float* w = (warp == 0) ? (ln3w + l*DD) : (ln1w + l*DD);
                const float* b = (warp == 0) ? (ln3b + l*DD) : (ln1b + l*DD);
                ln_row(g_x0 + warp*DD, addv, w, b, sh + warp*DD);
            }
            __syncthreads();
            if (blockIdx.x == 0)
                for (int i = tid; i < 7*DD; i += NTHR) g_h[i] = sh[i];
            for (int t = gw; t < 2*FF; t += NWARP) {
                if (t < FF) {
                    const float4* wr = (const float4*)(f1w1 + ((size_t)l*FF + t)*DD);
                    float4 wv[4];
#pragma unroll
                    for (int i = 0; i < 4; i++) wv[i] = __ldg(&wr[lane + 32*i]);
                    float bias = f1b1[l*FF + t];
                    for (int r = 1; r < 7; r++) {
                        const float4* s4 = (const float4*)(sh + r*DD);
                        float a = 0.f;
#pragma unroll
                        for (int i = 0; i < 4; i++) a += d4(wv[i], s4[lane + 32*i]);
                        a = wred(a);
                        if (lane == 0) g_hid[r*FF + t] = fmaxf(a + bias, 0.f);
                    }
                } else {
                    int e = t - FF;
                    const float4* wr = (const float4*)(f2w1 + ((size_t)l*FF + e)*DD);
                    const float4* s4 = (const float4*)sh;
                    float a = 0.f;
#pragma unroll
                    for (int i = 0; i < 4; i++) a += d4(__ldg(&wr[lane + 32*i]), s4[lane + 32*i]);
                    a = wred(a);
                    if (lane == 0) g_hid[e] = fmaxf(a + f2b1[l*FF + e], 0.f);
                }
            }
        }
        gridbar();

        // ---- s7: FFN down + residual ----
        {
            float* shid = sm;  // 14336
            for (int i = tid; i < 7*FF; i += NTHR) shid[i] = g_hid[i];
            __syncthreads();
            for (int t = gw; t < 2*DD; t += NWARP) {
                if (t < DD) {
                    const float4* wr = (const float4*)(f1w2 + ((size_t)l*DD + t)*FF);
                    float acc[6] = {0,0,0,0,0,0};
#pragma unroll
                    for (int i = 0; i < 16; i++) {
                        float4 w4 = __ldg(&wr[lane + 32*i]);
#pragma unroll
                        for (int r = 0; r < 6; r++) {
                            const float4* h4 = (const float4*)(shid + (r+1)*FF);
                            acc[r] += d4(w4, h4[lane + 32*i]);
                        }
                    }
                    float bias = f1b2[l*DD + t];
#pragma unroll
                    for (int r = 0; r < 6; r++) {
                        float a = wred(acc[r]);
                        if (lane == 0) g_y[(r+1)*DD + t] = a + bias + g_h[(r+1)*DD + t];
                    }
                } else {
                    int e = t - DD;
                    const float4* wr = (const float4*)(f2w2 + ((size_t)l*DD + e)*FF);
                    const float4* h4 = (const float4*)shid;
                    float a = 0.f;
#pragma unroll
                    for (int i = 0; i < 16; i++) a += d4(__ldg(&wr[lane + 32*i]), h4[lane + 32*i]);
                    a = wred(a);
                    if (lane == 0) g_y[e] = a + f2b2[l*DD + e] + g_h[e];
                }
            }
        }
        gridbar();
    }

    // ---- output: final LN24 of g_y -> out ----
    if (blockIdx.x == 0 && warp < 7) {
        const float* w = (warp == 0) ? (ln4w + 5*DD) : (ln2w + 5*DD);
        const float* b = (warp == 0) ? (ln4b + 5*DD) : (ln2b + 5*DD);
        ln_row(g_y + warp*DD, nullptr, w, b, out + warp*DD);
    }
}

#define SMEM_BYTES 73728

extern "C" void kernel_launch(void* const* d_in, const int* in_sizes, int n_in,
                              void* d_out, int out_size) {
    cudaFuncSetAttribute(fused_kernel, cudaFuncAttributeMaxDynamicSharedMemorySize, SMEM_BYTES);
    fused_kernel<<<NBLK, NTHR, SMEM_BYTES>>>(
        (const float*)d_in[0],  (const float*)d_in[1],
        (const float*)d_in[2],  (const float*)d_in[3],
        (const float*)d_in[4],  (const float*)d_in[5],
        (const float*)d_in[6],  (const float*)d_in[7],
        (const float*)d_in[8],  (const float*)d_in[9],
        (const float*)d_in[10], (const float*)d_in[11],
        (const float*)d_in[12], (const float*)d_in[13],
        (const float*)d_in[14], (const float*)d_in[15],
        (const float*)d_in[16], (const float*)d_in[17],
        (const float*)d_in[18], (const float*)d_in[19],
        (const float*)d_in[20], (const float*)d_in[21],
        (const float*)d_in[22], (const float*)d_in[23],
        (const float*)d_in[24], (const float*)d_in[25],
        (float*)d_out);
}

// round 3
// speedup vs baseline: 3.4304x; 1.2478x over previous
#include <cuda_runtime.h>

#define NBLK 148
#define NTHR 512
#define NWARP (NBLK*16)
#define NL 6
#define DD 512
#define FF 2048
#define TD 1536

// ---------------- device scratch ----------------
__device__ __align__(16) float g_src35[35*DD];
__device__ __align__(16) float g_kv[NL*5*7*1024];
__device__ __align__(16) float g_q0[NL*5*DD];
__device__ __align__(16) float g_ctx5[NL*5*DD];
__device__ __align__(16) float g_vm[NL*5*DD];
__device__ __align__(16) float g_aggv[NL*DD];
__device__ __align__(16) float g_x0[7*DD];
__device__ __align__(16) float g_qkv0[7*TD];
__device__ __align__(16) float g_msgN[6*DD];
__device__ __align__(16) float g_aggn[DD];
__device__ __align__(16) float g_h[7*DD];
__device__ __align__(16) float g_hid[7*FF];
__device__ __align__(16) float g_y[7*DD];
__device__ unsigned g_bar;

// ---------------- helpers ----------------
__device__ __forceinline__ float wred(float v) {
#pragma unroll
    for (int o = 16; o; o >>= 1) v += __shfl_xor_sync(0xffffffffu, v, o);
    return v;
}
__device__ __forceinline__ float d4(float4 a, float4 b) {
    return fmaf(a.x, b.x, fmaf(a.y, b.y, fmaf(a.z, b.z, a.w * b.w)));
}
__device__ __forceinline__ void gridbar() {
    __syncthreads();
    if (threadIdx.x == 0) {
        __threadfence();
        unsigned old = atomicAdd(&g_bar, 1u);
        unsigned target = (old / NBLK + 1u) * NBLK;
        while (*((volatile unsigned*)&g_bar) < target) {}
    }
    __syncthreads();
    __threadfence();
}
// L2 prefetch of nfloats starting at base; grid-cooperative
__device__ __forceinline__ void pf_range(const float* base, int nfloats, int gt) {
    const char* p = (const char*)base;
    int nlines = nfloats >> 5;   // 128B lines
    for (int i = gt; i < nlines; i += NBLK*NTHR)
        asm volatile("prefetch.global.L2 [%0];" :: "l"(p + (size_t)i*128));
}
// warp-collective LN of a 512-row; add may be null
__device__ __forceinline__ void ln_row(const float* __restrict__ x,
                                       const float* __restrict__ add,
                                       const float* __restrict__ w,
                                       const float* __restrict__ b,
                                       float* __restrict__ out) {
    int lane = threadIdx.x & 31;
    float v[16]; float s = 0.f;
#pragma unroll
    for (int j = 0; j < 16; j++) {
        float t = x[j*32 + lane];
        if (add) t += add[j*32 + lane];
        v[j] = t; s += t;
    }
    s = wred(s);
    float mu = s * (1.f/512.f);
    float q = 0.f;
#pragma unroll
    for (int j = 0; j < 16; j++) { float d = v[j] - mu; q += d*d; }
    q = wred(q);
    float rs = rsqrtf(q * (1.f/512.f) + 1e-5f);
#pragma unroll
    for (int j = 0; j < 16; j++)
        out[j*32 + lane] = (v[j] - mu) * rs * w[j*32 + lane] + b[j*32 + lane];
}

__global__ void __launch_bounds__(NTHR)
fused_kernel(const float* __restrict__ feat, const float* __restrict__ role,
             const float* __restrict__ in_w, const float* __restrict__ in_b,
             const float* __restrict__ out_w, const float* __restrict__ out_b,
             const float* __restrict__ ln1w, const float* __restrict__ ln1b,
             const float* __restrict__ ln2w, const float* __restrict__ ln2b,
             const float* __restrict__ ln3w, const float* __restrict__ ln3b,
             const float* __restrict__ ln4w, const float* __restrict__ ln4b,
             const float* __restrict__ f1w1, const float* __restrict__ f1b1,
             const float* __restrict__ f1w2, const float* __restrict__ f1b2,
             const float* __restrict__ f2w1, const float* __restrict__ f2b1,
             const float* __restrict__ f2w2, const float* __restrict__ f2b2,
             const float* __restrict__ a1w, const float* __restrict__ a1b,
             const float* __restrict__ a2w, const float* __restrict__ a2b,
             float* __restrict__ out)
{
    extern __shared__ float sm[];
    const int tid = threadIdx.x, lane = tid & 31, warp = tid >> 5;
    const int gw = blockIdx.x * (NTHR/32) + warp;
    const int gt = blockIdx.x * NTHR + tid;

    // ---- Phase A: src for batches 1..5; prefetch in_w (used next in P1) ----
    pf_range(in_w, NL*TD*DD, gt);
    for (int i = gt; i < 35*DD; i += NBLK*NTHR) {
        int b5 = i / (7*DD); int rem = i % (7*DD); int s = rem / DD; int d = rem % DD;
        float v = feat[((b5+1)*7 + s)*DD + d];
        if (s > 0) v += role[((b5+1)*6 + (s-1))*DD + d];
        g_src35[i] = v;
    }
    gridbar();

    // ---- Phase P1: K,V for all (l,b>=1,s) and Q(token0) ----
    pf_range(out_w, NL*DD*DD, gt);          // used in P2b
    pf_range(a1w, NL*DD*2560, gt);          // used in P3
    for (int i = tid; i < 35*DD; i += NTHR) sm[i] = g_src35[i];
    __syncthreads();
    for (int t = gw; t < NL*1024 + NL*DD; t += NWARP) {
        if (t < NL*1024) {
            int l = t >> 10, e = t & 1023;
            const float4* wr = (const float4*)(in_w + ((size_t)l*TD + 512 + e)*DD);
            float4 wv[4];
#pragma unroll
            for (int i = 0; i < 4; i++) wv[i] = __ldg(&wr[lane + 32*i]);
            float bias = in_b[l*TD + 512 + e];
            for (int bs = 0; bs < 35; bs++) {
                const float4* s4 = (const float4*)(sm + bs*DD);
                float a = 0.f;
#pragma unroll
                for (int i = 0; i < 4; i++) a += d4(wv[i], s4[lane + 32*i]);
                a = wred(a);
                if (lane == 0)
                    g_kv[((size_t)(l*5 + bs/7)*7 + bs%7)*1024 + e] = a + bias;
            }
        } else {
            int t2 = t - NL*1024;
            int l = t2 / DD, e = t2 % DD;
            const float4* wr = (const float4*)(in_w + ((size_t)l*TD + e)*DD);
            float4 wv[4];
#pragma unroll
            for (int i = 0; i < 4; i++) wv[i] = __ldg(&wr[lane + 32*i]);
            float bias = in_b[l*TD + e];
            for (int b5 = 0; b5 < 5; b5++) {
                const float4* s4 = (const float4*)(sm + (b5*7)*DD);
                float a = 0.f;
#pragma unroll
                for (int i = 0; i < 4; i++) a += d4(wv[i], s4[lane + 32*i]);
                a = wred(a);
                if (lane == 0) g_q0[(l*5 + b5)*DD + e] = a + bias;
            }
        }
    }
    gridbar();

    // ---- Phase P2a: attention token0 for (l, b>=1): 30 CTA tasks ----
    pf_range(f1w1, FF*DD, gt);              // layer 0 FFN-up weights
    pf_range(f2w1, FF*DD, gt);
    if (blockIdx.x < 30) {
        int l = blockIdx.x / 5, b5 = blockIdx.x % 5;
        float* sq = sm; float* sk = sm + DD; float* satt = sm + DD + 7*DD;
        const float* kvb = g_kv + (size_t)(l*5 + b5)*7*1024;
        for (int i = tid; i < DD; i += NTHR) sq[i] = g_q0[(l*5 + b5)*DD + i];
        for (int i = tid; i < 7*DD; i += NTHR) { int s = i >> 9, d = i & 511; sk[i] = kvb[s*1024 + d]; }
        __syncthreads();
        if (tid < 56) {
            int h = tid / 7, s = tid % 7;
            float a = 0.f;
            for (int d = 0; d < 64; d++) a += sq[h*64 + d] * sk[s*DD + h*64 + d];
            satt[tid] = a * 0.125f;
        }
        __syncthreads();
        if (tid < 8) {
            float m = -1e30f;
            for (int s = 0; s < 7; s++) m = fmaxf(m, satt[tid*7 + s]);
            float e[7], su = 0.f;
            for (int s = 0; s < 7; s++) { e[s] = expf(satt[tid*7 + s] - m); su += e[s]; }
            for (int s = 0; s < 7; s++) satt[tid*7 + s] = e[s] / su;
        }
        __syncthreads();
        for (int ch = tid; ch < DD; ch += NTHR) {
            int h = ch >> 6;
            float a = 0.f;
            for (int s = 0; s < 7; s++) a += satt[h*7 + s] * kvb[s*1024 + 512 + ch];
            g_ctx5[(l*5 + b5)*DD + ch] = a;
        }
    }
    gridbar();

    // ---- Phase P2b: verb msgs ----
    pf_range(a2w, DD*3072, gt);             // layer 0 a2w
    for (int i = tid; i < 30*DD; i += NTHR) sm[i] = g_ctx5[i];
    __syncthreads();
    for (int t = gw; t < NL*DD; t += NWARP) {
        int l = t / DD, e = t % DD;
        const float4* wr = (const float4*)(out_w + ((size_t)l*DD + e)*DD);
        float4 wv[4];
#pragma unroll
        for (int i = 0; i < 4; i++) wv[i] = __ldg(&wr[lane + 32*i]);
        float bias = out_b[l*DD + e];
        for (int b5 = 0; b5 < 5; b5++) {
            const float4* s4 = (const float4*)(sm + (l*5 + b5)*DD);
            float a = 0.f;
#pragma unroll
            for (int i = 0; i < 4; i++) a += d4(wv[i], s4[lane + 32*i]);
            a = wred(a);
            if (lane == 0) g_vm[(l*5 + b5)*DD + e] = a + bias;
        }
    }
    gridbar();

    // ---- Phase P3: agg_verb for all layers ----
    pf_range(f1w2, DD*FF, gt);              // layer 0 FFN-down weights
    pf_range(f2w2, DD*FF, gt);
    for (int i = tid; i < 30*DD; i += NTHR) sm[i] = g_vm[i];
    __syncthreads();
    for (int t = gw; t < NL*DD; t += NWARP) {
        int l = t / DD, e = t % DD;
        const float4* wr = (const float4*)(a1w + ((size_t)l*DD + e)*2560);
        const float4* s4 = (const float4*)(sm + l*5*DD);
        float a = 0.f;
#pragma unroll
        for (int i = 0; i < 20; i++) a += d4(__ldg(&wr[lane + 32*i]), s4[lane + 32*i]);
        a = wred(a);
        if (lane == 0) g_aggv[l*DD + e] = 1.f / (1.f + expf(-(a + a1b[l*DD + e])));
    }
    gridbar();

    // ================= serial layer loop =================
    for (int l = 0; l < NL; l++) {
        // ---- s1: LN24(prev) redundant, src = x0 + role, qkv ----
        // prefetch this layer's FFN-up + a2w (used in s4/s6)
        pf_range(a2w + (size_t)l*DD*3072, DD*3072, gt);
        pf_range(f1w1 + (size_t)l*FF*DD, FF*DD, gt);
        pf_range(f2w1 + (size_t)l*FF*DD, FF*DD, gt);
        float* sx0 = sm;           // 3584
        float* ssrc = sm + 3584;   // 3584
        if (l == 0) {
            for (int i = tid; i < 7*DD; i += NTHR) sx0[i] = feat[i];
        } else {
            if (warp < 7) {
                const float* w = (warp == 0) ? (ln4w + (l-1)*DD) : (ln2w + (l-1)*DD);
                const float* b = (warp == 0) ? (ln4b + (l-1)*DD) : (ln2b + (l-1)*DD);
                ln_row(g_y + warp*DD, nullptr, w, b, sx0 + warp*DD);
            }
        }
        __syncthreads();
        for (int i = tid; i < 7*DD; i += NTHR) {
            int s = i >> 9, d = i & 511;
            float v = sx0[i];
            if (s > 0) v += role[(s-1)*DD + d];
            ssrc[i] = v;
        }
        if (blockIdx.x == 0)
            for (int i = tid; i < 7*DD; i += NTHR) g_x0[i] = sx0[i];
        __syncthreads();
        for (int t = gw; t < TD; t += NWARP) {
            const float4* wr = (const float4*)(in_w + ((size_t)l*TD + t)*DD);
            float4 wv[4];
#pragma unroll
            for (int i = 0; i < 4; i++) wv[i] = __ldg(&wr[lane + 32*i]);
            float bias = in_b[l*TD + t];
            for (int s = 0; s < 7; s++) {
                const float4* s4 = (const float4*)(ssrc + s*DD);
                float a = 0.f;
#pragma unroll
                for (int i = 0; i < 4; i++) a += d4(wv[i], s4[lane + 32*i]);
                a = wred(a);
                if (lane == 0) g_qkv0[s*TD + t] = a + bias;
            }
        }
        gridbar();

        // ---- s3: attention (redundant per CTA) + msg out-proj ----
        {
            // prefetch FFN-down (used in s7)
            pf_range(f1w2 + (size_t)l*DD*FF, DD*FF, gt);
            pf_range(f2w2 + (size_t)l*DD*FF, DD*FF, gt);
            float* sqkv = sm;              // 10752
            float* sctx = sm + 10752;      // 3072
            float* satt = sm + 13824;      // 336
            for (int i = tid; i < 7*TD; i += NTHR) sqkv[i] = g_qkv0[i];
            __syncthreads();
            for (int t = tid; t < 336; t += NTHR) {
                int qi = t / 56, r = t % 56, h = r / 7, s = r % 7;
                float a = 0.f;
                for (int d = 0; d < 64; d++)
                    a += sqkv[(qi+1)*TD + h*64 + d] * sqkv[s*TD + 512 + h*64 + d];
                satt[t] = a * 0.125f;
            }
            __syncthreads();
            if (tid < 48) {
                float m = -1e30f;
                for (int s = 0; s < 7; s++) m = fmaxf(m, satt[tid*7 + s]);
                float e[7], su = 0.f;
                for (int s = 0; s < 7; s++) { e[s] = expf(satt[tid*7 + s] - m); su += e[s]; }
                for (int s = 0; s < 7; s++) satt[tid*7 + s] = e[s] / su;
            }
            __syncthreads();
            for (int i = tid; i < 6*DD; i += NTHR) {
                int qi = i >> 9, ch = i & 511, h = ch >> 6;
                float a = 0.f;
                for (int s = 0; s < 7; s++) a += satt[qi*56 + h*7 + s] * sqkv[s*TD + 1024 + ch];
                sctx[i] = a;
            }
            __syncthreads();
            for (int t = gw; t < DD; t += NWARP) {
                const float4* wr = (const float4*)(out_w + ((size_t)l*DD + t)*DD);
                float4 wv[4];
#pragma unroll
                for (int i = 0; i < 4; i++) wv[i] = __ldg(&wr[lane + 32*i]);
                float bias = out_b[l*DD + t];
                for (int r = 0; r < 6; r++) {
                    const float4* s4 = (const float4*)(sctx + r*DD);
                    float a = 0.f;
#pragma unroll
                    for (int i = 0; i < 4; i++) a += d4(wv[i], s4[lane + 32*i]);
                    a = wred(a);
                    if (lane == 0) g_msgN[r*DD + t] = a + bias;
                }
            }
        }
        gridbar();

        // ---- s4: agg_noun ----
        for (int i = tid; i < 6*DD; i += NTHR) sm[i] = g_msgN[i];
        __syncthreads();
        for (int t = gw; t < DD; t += NWARP) {
            const float4* wr = (const float4*)(a2w + ((size_t)l*DD + t)*3072);
            const float4* s4 = (const float4*)sm;
            float a = 0.f;
#pragma unroll
            for (int i = 0; i < 24; i++) a += d4(__ldg(&wr[lane + 32*i]), s4[lane + 32*i]);
            a = wred(a);
            if (lane == 0) g_aggn[t] = 1.f / (1.f + expf(-(a + a2b[l*DD + t])));
        }
        gridbar();

        // ---- s6: LN13 (redundant) + FFN up ----
        {
            // prefetch next layer's qkv/out-proj weights
            if (l + 1 < NL) {
                pf_range(in_w + (size_t)(l+1)*TD*DD, TD*DD, gt);
                pf_range(out_w + (size_t)(l+1)*DD*DD, DD*DD, gt);
            }
            float* sh = sm;  // 3584
            if (warp < 7) {
                const float* addv = (warp == 0) ? g_aggn : (g_aggv + l*DD);
                const float* w = (warp == 0) ? (ln3w + l*DD) : (ln1w + l*DD);
                const float* b = (warp == 0) ? (ln3b + l*DD) : (ln1b + l*DD);
                ln_row(g_x0 + warp*DD, addv, w, b, sh + warp*DD);
            }
            __syncthreads();
            if (blockIdx.x == 0)
                for (int i = tid; i < 7*DD; i += NTHR) g_h[i] = sh[i];
            for (int t = gw; t < 2*FF; t += NWARP) {
                if (t < FF) {
                    const float4* wr = (const float4*)(f1w1 + ((size_t)l*FF + t)*DD);
                    float4 wv[4];
#pragma unroll
                    for (int i = 0; i < 4; i++) wv[i] = __ldg(&wr[lane + 32*i]);
                    float bias = f1b1[l*FF + t];
                    for (int r = 1; r < 7; r++) {
                        const float4* s4 = (const float4*)(sh + r*DD);
                        float a = 0.f;
#pragma unroll
                        for (int i = 0; i < 4; i++) a += d4(wv[i], s4[lane + 32*i]);
                        a = wred(a);
                        if (lane == 0) g_hid[r*FF + t] = fmaxf(a + bias, 0.f);
                    }
                } else {
                    int e = t - FF;
                    const float4* wr = (const float4*)(f2w1 + ((size_t)l*FF + e)*DD);
                    const float4* s4 = (const float4*)sh;
                    float a = 0.f;
#pragma unroll
                    for (int i = 0; i < 4; i++) a += d4(__ldg(&wr[lane + 32*i]), s4[lane + 32*i]);
                    a = wred(a);
                    if (lane == 0) g_hid[e] = fmaxf(a + f2b1[l*FF + e], 0.f);
                }
            }
        }
        gridbar();

        // ---- s7: FFN down + residual ----
        {
            float* shid = sm;  // 14336
            for (int i = tid; i < 7*FF; i += NTHR) shid[i] = g_hid[i];
            __syncthreads();
            for (int t = gw; t < 2*DD; t += NWARP) {
                if (t < DD) {
                    const float4* wr = (const float4*)(f1w2 + ((size_t)l*DD + t)*FF);
                    float acc[6] = {0,0,0,0,0,0};
#pragma unroll
                    for (int i = 0; i < 16; i++) {
                        float4 w4 = __ldg(&wr[lane + 32*i]);
#pragma unroll
                        for (int r = 0; r < 6; r++) {
                            const float4* h4 = (const float4*)(shid + (r+1)*FF);
                            acc[r] += d4(w4, h4[lane + 32*i]);
                        }
                    }
                    float bias = f1b2[l*DD + t];
#pragma unroll
                    for (int r = 0; r < 6; r++) {
                        float a = wred(acc[r]);
                        if (lane == 0) g_y[(r+1)*DD + t] = a + bias + g_h[(r+1)*DD + t];
                    }
                } else {
                    int e = t - DD;
                    const float4* wr = (const float4*)(f2w2 + ((size_t)l*DD + e)*FF);
                    const float4* h4 = (const float4*)shid;
                    float a = 0.f;
#pragma unroll
                    for (int i = 0; i < 16; i++) a += d4(__ldg(&wr[lane + 32*i]), h4[lane + 32*i]);
                    a = wred(a);
                    if (lane == 0) g_y[e] = a + f2b2[l*DD + e] + g_h[e];
                }
            }
        }
        gridbar();
    }

    // ---- output: final LN24 of g_y -> out ----
    if (blockIdx.x == 0 && warp < 7) {
        const float* w = (warp == 0) ? (ln4w + 5*DD) : (ln2w + 5*DD);
        const float* b = (warp == 0) ? (ln4b + 5*DD) : (ln2b + 5*DD);
        ln_row(g_y + warp*DD, nullptr, w, b, out + warp*DD);
    }
}

#define SMEM_BYTES 73728

extern "C" void kernel_launch(void* const* d_in, const int* in_sizes, int n_in,
                              void* d_out, int out_size) {
    cudaFuncSetAttribute(fused_kernel, cudaFuncAttributeMaxDynamicSharedMemorySize, SMEM_BYTES);
    fused_kernel<<<NBLK, NTHR, SMEM_BYTES>>>(
        (const float*)d_in[0],  (const float*)d_in[1],
        (const float*)d_in[2],  (const float*)d_in[3],
        (const float*)d_in[4],  (const float*)d_in[5],
        (const float*)d_in[6],  (const float*)d_in[7],
        (const float*)d_in[8],  (const float*)d_in[9],
        (const float*)d_in[10], (const float*)d_in[11],
        (const float*)d_in[12], (const float*)d_in[13],
        (const float*)d_in[14], (const float*)d_in[15],
        (const float*)d_in[16], (const float*)d_in[17],
        (const float*)d_in[18], (const float*)d_in[19],
        (const float*)d_in[20], (const float*)d_in[21],
        (const float*)d_in[22], (const float*)d_in[23],
        (const float*)d_in[24], (const float*)d_in[25],
        (float*)d_out);
}

// round 4
// speedup vs baseline: 3.4780x; 1.0139x over previous
#include <cuda_runtime.h>

#define NBLK 148
#define NTHR 512
#define NWARP (NBLK*16)
#define NL 6
#define DD 512
#define FF 2048
#define TD 1536

// ---------------- device scratch ----------------
__device__ __align__(16) float g_src35[35*DD];
__device__ __align__(16) float g_kv[NL*5*7*1024];
__device__ __align__(16) float g_q0[NL*5*DD];
__device__ __align__(16) float g_ctx5[NL*5*DD];
__device__ __align__(16) float g_vm[NL*5*DD];
__device__ __align__(16) float g_aggv[NL*DD];
__device__ __align__(16) float g_x0[7*DD];
__device__ __align__(16) float g_qkv0[7*TD];
__device__ __align__(16) float g_msgN[6*DD];
__device__ __align__(16) float g_aggn[DD];
__device__ __align__(16) float g_h[7*DD];
__device__ __align__(16) float g_hid[7*FF];
__device__ __align__(16) float g_y[7*DD];
__device__ unsigned g_bar;

// ---------------- helpers ----------------
__device__ __forceinline__ float wred(float v) {
#pragma unroll
    for (int o = 16; o; o >>= 1) v += __shfl_xor_sync(0xffffffffu, v, o);
    return v;
}
__device__ __forceinline__ float d4(float4 a, float4 b) {
    return fmaf(a.x, b.x, fmaf(a.y, b.y, fmaf(a.z, b.z, a.w * b.w)));
}
__device__ __forceinline__ void gridbar() {
    __syncthreads();
    if (threadIdx.x == 0) {
        unsigned old;
        asm volatile("atom.release.gpu.add.u32 %0, [%1], %2;"
                     : "=r"(old) : "l"(&g_bar), "r"(1u) : "memory");
        unsigned target = (old / NBLK + 1u) * NBLK;
        unsigned cur;
        do {
            asm volatile("ld.acquire.gpu.u32 %0, [%1];" : "=r"(cur) : "l"(&g_bar) : "memory");
        } while (cur < target);
    }
    __syncthreads();
}
// L2 prefetch of nfloats starting at base; grid-cooperative
__device__ __forceinline__ void pf_range(const float* base, int nfloats, int gt) {
    const char* p = (const char*)base;
    int nlines = nfloats >> 5;   // 128B lines
    for (int i = gt; i < nlines; i += NBLK*NTHR)
        asm volatile("prefetch.global.L2 [%0];" :: "l"(p + (size_t)i*128));
}
// load a 512-float weight row into 4 float4 regs (coalesced per warp)
__device__ __forceinline__ void ldw(const float* w, float4* wv) {
    const float4* wr = (const float4*)w;
    int lane = threadIdx.x & 31;
#pragma unroll
    for (int i = 0; i < 4; i++) wv[i] = __ldg(&wr[lane + 32*i]);
}
// K dots of length 512 against smem vectors at stride STR, with interleaved
// butterfly reductions (independent shfl chains).
template<int K, int STR>
__device__ __forceinline__ void dotK(const float4* wv, const float* smbase, float* res) {
    int lane = threadIdx.x & 31;
    float acc[K];
#pragma unroll
    for (int k = 0; k < K; k++) {
        const float4* s4 = (const float4*)(smbase + k*STR);
        float a0 = d4(wv[0], s4[lane]);
        float a1 = d4(wv[1], s4[lane+32]);
        float a2 = d4(wv[2], s4[lane+64]);
        float a3 = d4(wv[3], s4[lane+96]);
        acc[k] = (a0 + a1) + (a2 + a3);
    }
#pragma unroll
    for (int o = 16; o; o >>= 1)
#pragma unroll
        for (int k = 0; k < K; k++)
            acc[k] += __shfl_xor_sync(0xffffffffu, acc[k], o);
#pragma unroll
    for (int k = 0; k < K; k++) res[k] = acc[k];
}
// single long dot (len = 128*NIT floats) with 4 independent accumulators
template<int NIT>
__device__ __forceinline__ float dot_long(const float* w, const float* smbase) {
    int lane = threadIdx.x & 31;
    const float4* wr = (const float4*)w;
    const float4* s4 = (const float4*)smbase;
    float a[4] = {0.f, 0.f, 0.f, 0.f};
#pragma unroll
    for (int i = 0; i < NIT; i += 4) {
        a[0] += d4(__ldg(&wr[lane + 32*(i+0)]), s4[lane + 32*(i+0)]);
        a[1] += d4(__ldg(&wr[lane + 32*(i+1)]), s4[lane + 32*(i+1)]);
        a[2] += d4(__ldg(&wr[lane + 32*(i+2)]), s4[lane + 32*(i+2)]);
        a[3] += d4(__ldg(&wr[lane + 32*(i+3)]), s4[lane + 32*(i+3)]);
    }
    return wred((a[0] + a[1]) + (a[2] + a[3]));
}
// warp-collective LN of a 512-row; add may be null
__device__ __forceinline__ void ln_row(const float* __restrict__ x,
                                       const float* __restrict__ add,
                                       const float* __restrict__ w,
                                       const float* __restrict__ b,
                                       float* __restrict__ out) {
    int lane = threadIdx.x & 31;
    float v[16]; float s = 0.f;
#pragma unroll
    for (int j = 0; j < 16; j++) {
        float t = x[j*32 + lane];
        if (add) t += add[j*32 + lane];
        v[j] = t; s += t;
    }
    s = wred(s);
    float mu = s * (1.f/512.f);
    float q = 0.f;
#pragma unroll
    for (int j = 0; j < 16; j++) { float d = v[j] - mu; q += d*d; }
    q = wred(q);
    float rs = rsqrtf(q * (1.f/512.f) + 1e-5f);
#pragma unroll
    for (int j = 0; j < 16; j++)
        out[j*32 + lane] = (v[j] - mu) * rs * w[j*32 + lane] + b[j*32 + lane];
}

__global__ void __launch_bounds__(NTHR)
fused_kernel(const float* __restrict__ feat, const float* __restrict__ role,
             const float* __restrict__ in_w, const float* __restrict__ in_b,
             const float* __restrict__ out_w, const float* __restrict__ out_b,
             const float* __restrict__ ln1w, const float* __restrict__ ln1b,
             const float* __restrict__ ln2w, const float* __restrict__ ln2b,
             const float* __restrict__ ln3w, const float* __restrict__ ln3b,
             const float* __restrict__ ln4w, const float* __restrict__ ln4b,
             const float* __restrict__ f1w1, const float* __restrict__ f1b1,
             const float* __restrict__ f1w2, const float* __restrict__ f1b2,
             const float* __restrict__ f2w1, const float* __restrict__ f2b1,
             const float* __restrict__ f2w2, const float* __restrict__ f2b2,
             const float* __restrict__ a1w, const float* __restrict__ a1b,
             const float* __restrict__ a2w, const float* __restrict__ a2b,
             float* __restrict__ out)
{
    extern __shared__ float sm[];
    const int tid = threadIdx.x, lane = tid & 31, warp = tid >> 5;
    const int gw = blockIdx.x * (NTHR/32) + warp;
    const int gt = blockIdx.x * NTHR + tid;

    // ---- Phase A ----
    pf_range(in_w, NL*TD*DD, gt);
    for (int i = gt; i < 35*DD; i += NBLK*NTHR) {
        int b5 = i / (7*DD); int rem = i % (7*DD); int s = rem / DD; int d = rem % DD;
        float v = feat[((b5+1)*7 + s)*DD + d];
        if (s > 0) v += role[((b5+1)*6 + (s-1))*DD + d];
        g_src35[i] = v;
    }
    gridbar();

    // ---- Phase P1: K,V for (l,b>=1,s) and Q(token0) ----
    pf_range(out_w, NL*DD*DD, gt);
    pf_range(a1w, NL*DD*2560, gt);
    for (int i = tid; i < 35*DD; i += NTHR) sm[i] = g_src35[i];
    __syncthreads();
    for (int t = gw; t < NL*1024 + NL*DD; t += NWARP) {
        if (t < NL*1024) {
            int l = t >> 10, e = t & 1023;
            float4 wv[4]; ldw(in_w + ((size_t)l*TD + 512 + e)*DD, wv);
            float bias = in_b[l*TD + 512 + e];
            float res[7];
#pragma unroll
            for (int g = 0; g < 5; g++) {
                dotK<7, DD>(wv, sm + g*7*DD, res);
                if (lane == 0) {
#pragma unroll
                    for (int j = 0; j < 7; j++)
                        g_kv[((size_t)(l*5 + g)*7 + j)*1024 + e] = res[j] + bias;
                }
            }
        } else {
            int t2 = t - NL*1024;
            int l = t2 / DD, e = t2 % DD;
            float4 wv[4]; ldw(in_w + ((size_t)l*TD + e)*DD, wv);
            float bias = in_b[l*TD + e];
            float res[5];
            dotK<5, 7*DD>(wv, sm, res);
            if (lane == 0) {
#pragma unroll
                for (int j = 0; j < 5; j++)
                    g_q0[(l*5 + j)*DD + e] = res[j] + bias;
            }
        }
    }
    gridbar();

    // ---- Phase P2a: attention token0 for (l, b>=1) ----
    pf_range(f1w1, FF*DD, gt);
    pf_range(f2w1, FF*DD, gt);
    if (blockIdx.x < 30) {
        int l = blockIdx.x / 5, b5 = blockIdx.x % 5;
        float* sq = sm; float* sk = sm + DD; float* satt = sm + DD + 7*DD;
        const float* kvb = g_kv + (size_t)(l*5 + b5)*7*1024;
        for (int i = tid; i < DD; i += NTHR) sq[i] = g_q0[(l*5 + b5)*DD + i];
        for (int i = tid; i < 7*DD; i += NTHR) { int s = i >> 9, d = i & 511; sk[i] = kvb[s*1024 + d]; }
        __syncthreads();
        if (tid < 56) {
            int h = tid / 7, s = tid % 7;
            float a = 0.f;
            for (int d = 0; d < 64; d++) a += sq[h*64 + d] * sk[s*DD + h*64 + d];
            satt[tid] = a * 0.125f;
        }
        __syncthreads();
        if (tid < 8) {
            float m = -1e30f;
            for (int s = 0; s < 7; s++) m = fmaxf(m, satt[tid*7 + s]);
            float e[7], su = 0.f;
            for (int s = 0; s < 7; s++) { e[s] = expf(satt[tid*7 + s] - m); su += e[s]; }
            for (int s = 0; s < 7; s++) satt[tid*7 + s] = e[s] / su;
        }
        __syncthreads();
        for (int ch = tid; ch < DD; ch += NTHR) {
            int h = ch >> 6;
            float a = 0.f;
            for (int s = 0; s < 7; s++) a += satt[h*7 + s] * kvb[s*1024 + 512 + ch];
            g_ctx5[(l*5 + b5)*DD + ch] = a;
        }
    }
    gridbar();

    // ---- Phase P2b: verb msgs ----
    pf_range(a2w, DD*3072, gt);
    for (int i = tid; i < 30*DD; i += NTHR) sm[i] = g_ctx5[i];
    __syncthreads();
    for (int t = gw; t < NL*DD; t += NWARP) {
        int l = t / DD, e = t % DD;
        float4 wv[4]; ldw(out_w + ((size_t)l*DD + e)*DD, wv);
        float bias = out_b[l*DD + e];
        float res[5];
        dotK<5, DD>(wv, sm + l*5*DD, res);
        if (lane == 0) {
#pragma unroll
            for (int j = 0; j < 5; j++)
                g_vm[(l*5 + j)*DD + e] = res[j] + bias;
        }
    }
    gridbar();

    // ---- Phase P3: agg_verb ----
    pf_range(f1w2, DD*FF, gt);
    pf_range(f2w2, DD*FF, gt);
    for (int i = tid; i < 30*DD; i += NTHR) sm[i] = g_vm[i];
    __syncthreads();
    for (int t = gw; t < NL*DD; t += NWARP) {
        int l = t / DD, e = t % DD;
        float a = dot_long<20>(a1w + ((size_t)l*DD + e)*2560, sm + l*5*DD);
        if (lane == 0) g_aggv[l*DD + e] = 1.f / (1.f + expf(-(a + a1b[l*DD + e])));
    }
    gridbar();

    // ================= serial layer loop =================
    for (int l = 0; l < NL; l++) {
        // ---- s1: LN24(prev) redundant, src = x0 + role, qkv ----
        pf_range(a2w + (size_t)l*DD*3072, DD*3072, gt);
        pf_range(f1w1 + (size_t)l*FF*DD, FF*DD, gt);
        pf_range(f2w1 + (size_t)l*FF*DD, FF*DD, gt);
        float* sx0 = sm;           // 3584
        float* ssrc = sm + 3584;   // 3584
        if (l == 0) {
            for (int i = tid; i < 7*DD; i += NTHR) sx0[i] = feat[i];
        } else {
            if (warp < 7) {
                const float* w = (warp == 0) ? (ln4w + (l-1)*DD) : (ln2w + (l-1)*DD);
                const float* b = (warp == 0) ? (ln4b + (l-1)*DD) : (ln2b + (l-1)*DD);
                ln_row(g_y + warp*DD, nullptr, w, b, sx0 + warp*DD);
            }
        }
        __syncthreads();
        for (int i = tid; i < 7*DD; i += NTHR) {
            int s = i >> 9, d = i & 511;
            float v = sx0[i];
            if (s > 0) v += role[(s-1)*DD + d];
            ssrc[i] = v;
        }
        if (blockIdx.x == 0)
            for (int i = tid; i < 7*DD; i += NTHR) g_x0[i] = sx0[i];
        __syncthreads();
        for (int t = gw; t < TD; t += NWARP) {
            float4 wv[4]; ldw(in_w + ((size_t)l*TD + t)*DD, wv);
            float bias = in_b[l*TD + t];
            float res[7];
            dotK<7, DD>(wv, ssrc, res);
            if (lane == 0) {
#pragma unroll
                for (int s = 0; s < 7; s++)
                    g_qkv0[s*TD + t] = res[s] + bias;
            }
        }
        gridbar();

        // ---- s3: attention (redundant per CTA) + msg out-proj ----
        {
            pf_range(f1w2 + (size_t)l*DD*FF, DD*FF, gt);
            pf_range(f2w2 + (size_t)l*DD*FF, DD*FF, gt);
            float* sqkv = sm;              // 10752
            float* sctx = sm + 10752;      // 3072
            float* satt = sm + 13824;      // 336
            for (int i = tid; i < 7*TD; i += NTHR) sqkv[i] = g_qkv0[i];
            __syncthreads();
            for (int t = tid; t < 336; t += NTHR) {
                int qi = t / 56, r = t % 56, h = r / 7, s = r % 7;
                float a = 0.f;
                for (int d = 0; d < 64; d++)
                    a += sqkv[(qi+1)*TD + h*64 + d] * sqkv[s*TD + 512 + h*64 + d];
                satt[t] = a * 0.125f;
            }
            __syncthreads();
            if (tid < 48) {
                float m = -1e30f;
                for (int s = 0; s < 7; s++) m = fmaxf(m, satt[tid*7 + s]);
                float e[7], su = 0.f;
                for (int s = 0; s < 7; s++) { e[s] = expf(satt[tid*7 + s] - m); su += e[s]; }
                for (int s = 0; s < 7; s++) satt[tid*7 + s] = e[s] / su;
            }
            __syncthreads();
            for (int i = tid; i < 6*DD; i += NTHR) {
                int qi = i >> 9, ch = i & 511, h = ch >> 6;
                float a = 0.f;
                for (int s = 0; s < 7; s++) a += satt[qi*56 + h*7 + s] * sqkv[s*TD + 1024 + ch];
                sctx[i] = a;
            }
            __syncthreads();
            for (int t = gw; t < DD; t += NWARP) {
                float4 wv[4]; ldw(out_w + ((size_t)l*DD + t)*DD, wv);
                float bias = out_b[l*DD + t];
                float res[6];
                dotK<6, DD>(wv, sctx, res);
                if (lane == 0) {
#pragma unroll
                    for (int r = 0; r < 6; r++)
                        g_msgN[r*DD + t] = res[r] + bias;
                }
            }
        }
        gridbar();

        // ---- s4: agg_noun ----
        for (int i = tid; i < 6*DD; i += NTHR) sm[i] = g_msgN[i];
        __syncthreads();
        for (int t = gw; t < DD; t += NWARP) {
            float a = dot_long<24>(a2w + ((size_t)l*DD + t)*3072, sm);
            if (lane == 0) g_aggn[t] = 1.f / (1.f + expf(-(a + a2b[l*DD + t])));
        }
        gridbar();

        // ---- s6: LN13 (redundant) + FFN up ----
        {
            if (l + 1 < NL) {
                pf_range(in_w + (size_t)(l+1)*TD*DD, TD*DD, gt);
                pf_range(out_w + (size_t)(l+1)*DD*DD, DD*DD, gt);
            }
            float* sh = sm;  // 3584
            if (warp < 7) {
                const float* addv = (warp == 0) ? g_aggn : (g_aggv + l*DD);
                const float* w = (warp == 0) ? (ln3w + l*DD) : (ln1w + l*DD);
                const float* b = (warp == 0) ? (ln3b + l*DD) : (ln1b + l*DD);
                ln_row(g_x0 + warp*DD, addv, w, b, sh + warp*DD);
            }
            __syncthreads();
            if (blockIdx.x == 0)
                for (int i = tid; i < 7*DD; i += NTHR) g_h[i] = sh[i];
            for (int t = gw; t < 2*FF; t += NWARP) {
                if (t < FF) {
                    float4 wv[4]; ldw(f1w1 + ((size_t)l*FF + t)*DD, wv);
                    float bias = f1b1[l*FF + t];
                    float res[6];
                    dotK<6, DD>(wv, sh + DD, res);
                    if (lane == 0) {
#pragma unroll
                        for (int r = 0; r < 6; r++)
                            g_hid[(r+1)*FF + t] = fmaxf(res[r] + bias, 0.f);
                    }
                } else {
                    int e = t - FF;
                    float4 wv[4]; ldw(f2w1 + ((size_t)l*FF + e)*DD, wv);
                    float res[1];
                    dotK<1, DD>(wv, sh, res);
                    if (lane == 0) g_hid[e] = fmaxf(res[0] + f2b1[l*FF + e], 0.f);
                }
            }
        }
        gridbar();

        // ---- s7: FFN down + residual ----
        {
            float* shid = sm;  // 14336
            for (int i = tid; i < 7*FF; i += NTHR) shid[i] = g_hid[i];
            __syncthreads();
            for (int t = gw; t < 2*DD; t += NWARP) {
                if (t < DD) {
                    const float4* wr = (const float4*)(f1w2 + ((size_t)l*DD + t)*FF);
                    float acc[6] = {0,0,0,0,0,0};
#pragma unroll
                    for (int i = 0; i < 16; i++) {
                        float4 w4 = __ldg(&wr[lane + 32*i]);
#pragma unroll
                        for (int r = 0; r < 6; r++)
                            acc[r] += d4(w4, ((const float4*)(shid + (r+1)*FF))[lane + 32*i]);
                    }
#pragma unroll
                    for (int o = 16; o; o >>= 1)
#pragma unroll
                        for (int r = 0; r < 6; r++)
                            acc[r] += __shfl_xor_sync(0xffffffffu, acc[r], o);
                    if (lane == 0) {
                        float bias = f1b2[l*DD + t];
#pragma unroll
                        for (int r = 0; r < 6; r++)
                            g_y[(r+1)*DD + t] = acc[r] + bias + g_h[(r+1)*DD + t];
                    }
                } else {
                    int e = t - DD;
                    float a = dot_long<16>(f2w2 + ((size_t)l*DD + e)*FF, shid);
                    if (lane == 0) g_y[e] = a + f2b2[l*DD + e] + g_h[e];
                }
            }
        }
        gridbar();
    }

    // ---- output: final LN24 of g_y -> out ----
    if (blockIdx.x == 0 && warp < 7) {
        const float* w = (warp == 0) ? (ln4w + 5*DD) : (ln2w + 5*DD);
        const float* b = (warp == 0) ? (ln4b + 5*DD) : (ln2b + 5*DD);
        ln_row(g_y + warp*DD, nullptr, w, b, out + warp*DD);
    }
}

#define SMEM_BYTES 73728

extern "C" void kernel_launch(void* const* d_in, const int* in_sizes, int n_in,
                              void* d_out, int out_size) {
    cudaFuncSetAttribute(fused_kernel, cudaFuncAttributeMaxDynamicSharedMemorySize, SMEM_BYTES);
    fused_kernel<<<NBLK, NTHR, SMEM_BYTES>>>(
        (const float*)d_in[0],  (const float*)d_in[1],
        (const float*)d_in[2],  (const float*)d_in[3],
        (const float*)d_in[4],  (const float*)d_in[5],
        (const float*)d_in[6],  (const float*)d_in[7],
        (const float*)d_in[8],  (const float*)d_in[9],
        (const float*)d_in[10], (const float*)d_in[11],
        (const float*)d_in[12], (const float*)d_in[13],
        (const float*)d_in[14], (const float*)d_in[15],
        (const float*)d_in[16], (const float*)d_in[17],
        (const float*)d_in[18], (const float*)d_in[19],
        (const float*)d_in[20], (const float*)d_in[21],
        (const float*)d_in[22], (const float*)d_in[23],
        (const float*)d_in[24], (const float*)d_in[25],
        (float*)d_out);
}